// round 3
// baseline (speedup 1.0000x reference)
#include <cuda_runtime.h>
#include <math.h>

#define NN 50000
#define NE 800000
#define HD 128
#define NG 64

// ---------------- scratch (device globals: allocation-free) ----------------
__device__ int      g_deg[NN];
__device__ int      g_fill[NN];
__device__ int      g_off[NN + 1];
__device__ int      g_csr_src[NE];
__device__ float    g_csr_w[NE];
__device__ float    g_S [NN * HD];   // GEMM output (support)
__device__ float    g_h1[NN * HD];
__device__ float    g_h2[NN * HD];
__device__ float    g_h3[NN * HD];
__device__ float    g_slin[NN];      // h @ wa (accumulated per layer)
__device__ float    g_score[NN];
__device__ float    g_poolsum[NG * 3 * HD];
__device__ unsigned g_poolmax[NG * 3 * HD];
__device__ int      g_gstart[NG + 1];

// monotonic float<->uint encoding for atomicMax on floats
__device__ __forceinline__ unsigned encf(float f) {
    unsigned u = __float_as_uint(f);
    return (u & 0x80000000u) ? ~u : (u | 0x80000000u);
}
__device__ __forceinline__ float decf(unsigned u) {
    return __uint_as_float((u & 0x80000000u) ? (u ^ 0x80000000u) : ~u);
}

// ---------------- packed fp32x2 helpers (sm_100+) --------------------------
__device__ __forceinline__ unsigned long long pk2(float a, float b) {
    unsigned long long r;
    asm("mov.b64 %0, {%1, %2};" : "=l"(r) : "f"(a), "f"(b));
    return r;
}
__device__ __forceinline__ void upk2(unsigned long long v, float& a, float& b) {
    asm("mov.b64 {%0, %1}, %2;" : "=f"(a), "=f"(b) : "l"(v));
}
__device__ __forceinline__ void ffma2(unsigned long long& d,
                                      unsigned long long a,
                                      unsigned long long b) {
    asm("fma.rn.f32x2 %0, %1, %2, %0;" : "+l"(d) : "l"(a), "l"(b));
}

// ---------------- init ----------------
__global__ void zero_kernel() {
    int i = blockIdx.x * blockDim.x + threadIdx.x;
    int stride = gridDim.x * blockDim.x;
    for (int j = i; j < NN; j += stride) { g_deg[j] = 0; g_fill[j] = 0; }
    for (int j = i; j < NG * 3 * HD; j += stride) { g_poolsum[j] = 0.f; g_poolmax[j] = 0u; }
    if (i < NG + 1) g_gstart[i] = 0;
}

// ---------------- CSR build (edge_index is int32: JAX x64 disabled) -------
__global__ void hist_kernel(const int* __restrict__ ei) {
    int e = blockIdx.x * blockDim.x + threadIdx.x;
    if (e < NE) {
        unsigned d = (unsigned)ei[NE + e];  // row 1 = dst
        if (d < NN) atomicAdd(&g_deg[d], 1);
    }
}

__global__ void scan_kernel() {
    __shared__ int sm[1024];
    const int ITEMS = 49;  // 1024*49 = 50176 >= 50000
    int t = threadIdx.x;
    int base = t * ITEMS;
    int s = 0;
    for (int i = 0; i < ITEMS; i++) {
        int idx = base + i;
        if (idx < NN) s += g_deg[idx];
    }
    sm[t] = s;
    __syncthreads();
    for (int d = 1; d < 1024; d <<= 1) {
        int v = 0;
        if (t >= d) v = sm[t - d];
        __syncthreads();
        sm[t] += v;
        __syncthreads();
    }
    int run = sm[t] - s;  // exclusive base for this chunk
    for (int i = 0; i < ITEMS; i++) {
        int idx = base + i;
        if (idx < NN) { g_off[idx] = run; run += g_deg[idx]; }
    }
    if (t == 1023) g_off[NN] = sm[1023];
}

__global__ void scatter_kernel(const int* __restrict__ ei,
                               const float* __restrict__ ew) {
    int e = blockIdx.x * blockDim.x + threadIdx.x;
    if (e >= NE) return;
    unsigned d = (unsigned)ei[NE + e];
    unsigned s = (unsigned)ei[e];
    if (d >= NN || s >= NN) return;
    int pos = g_off[d] + atomicAdd(&g_fill[d], 1);
    g_csr_src[pos] = (int)s;
    g_csr_w[pos] = ew[e];
}

__global__ void bounds_kernel(const int* __restrict__ gi) {
    int n = blockIdx.x * blockDim.x + threadIdx.x;
    if (n >= NN) return;
    int g = gi[n];
    if ((unsigned)g >= NG) return;
    if (n == 0) g_gstart[g] = 0;
    else if (gi[n - 1] != g) g_gstart[g] = n;
    if (n == NN - 1) g_gstart[NG] = NN;
}

__global__ void bounds_fix_kernel() {
    if (threadIdx.x == 0) {
        for (int g = NG - 1; g >= 1; g--)
            if (g_gstart[g] == 0 && g_gstart[g - 1] != 0) g_gstart[g] = g_gstart[g + 1];
    }
}

// ---------------- GEMM: S = X @ W  (X: [nrows,128], W: [128,128]) ---------
// block = 256 threads, tile = 64 rows x 128 cols, thread = 8 rows x 4 cols.
// Accumulators packed across row pairs -> fma.rn.f32x2 (2 FMA / issue slot).
__global__ void __launch_bounds__(256, 1)
gemm128_kernel(const float* __restrict__ X,
               const float* __restrict__ W,
               float* __restrict__ S, int nrows) {
    extern __shared__ float sh[];
    float* Wsh = sh;              // 128*128
    float* Xsh = sh + HD * HD;    // 64*128
    int tid = threadIdx.x;
    int rbase = blockIdx.x * 64;

#pragma unroll
    for (int i = 0; i < 16; i++) {
        int f = tid + i * 256;  // float4 idx, 4096 total
        ((float4*)Wsh)[f] = ((const float4*)W)[f];
    }
#pragma unroll
    for (int i = 0; i < 8; i++) {
        int f = tid + i * 256;  // float4 idx, 2048 total
        int row = rbase + (f >> 5);
        float4 v = make_float4(0.f, 0.f, 0.f, 0.f);
        if (row < nrows) v = ((const float4*)X)[row * 32 + (f & 31)];
        ((float4*)Xsh)[f] = v;
    }
    __syncthreads();

    int tx = tid & 31, ty = tid >> 5;
    int c0 = tx * 4, r0 = ty * 8;

    // acc[rp][c]: packed pair (row r0+2rp, row r0+2rp+1), column c0+c
    unsigned long long acc[4][4];
#pragma unroll
    for (int rp = 0; rp < 4; rp++)
#pragma unroll
        for (int c = 0; c < 4; c++) acc[rp][c] = 0ull;

#pragma unroll 2
    for (int k = 0; k < HD; k += 4) {
        float4 xv[8];
#pragma unroll
        for (int rr = 0; rr < 8; rr++)
            xv[rr] = *(float4*)&Xsh[(r0 + rr) * HD + k];
#pragma unroll
        for (int kk = 0; kk < 4; kk++) {
            float4 w = *(float4*)&Wsh[(k + kk) * HD + c0];
            unsigned long long wb0 = pk2(w.x, w.x);
            unsigned long long wb1 = pk2(w.y, w.y);
            unsigned long long wb2 = pk2(w.z, w.z);
            unsigned long long wb3 = pk2(w.w, w.w);
#pragma unroll
            for (int rp = 0; rp < 4; rp++) {
                float x0 = ((const float*)&xv[2 * rp])[kk];
                float x1 = ((const float*)&xv[2 * rp + 1])[kk];
                unsigned long long xp = pk2(x0, x1);
                ffma2(acc[rp][0], xp, wb0);
                ffma2(acc[rp][1], xp, wb1);
                ffma2(acc[rp][2], xp, wb2);
                ffma2(acc[rp][3], xp, wb3);
            }
        }
    }

#pragma unroll
    for (int rp = 0; rp < 4; rp++) {
        float4 o0, o1;
        upk2(acc[rp][0], o0.x, o1.x);
        upk2(acc[rp][1], o0.y, o1.y);
        upk2(acc[rp][2], o0.z, o1.z);
        upk2(acc[rp][3], o0.w, o1.w);
        int row = rbase + r0 + 2 * rp;
        if (row < nrows)     *(float4*)&S[row * HD + c0]       = o0;
        if (row + 1 < nrows) *(float4*)&S[(row + 1) * HD + c0] = o1;
    }
}

// ---------------- aggregation: out[n] = relu(b + sum_e w_e * S[src_e]) ----
// one warp per dst node; fused partial of slin = dot(out_row, wa_segment)
__global__ void agg_kernel(const float* __restrict__ S,
                           const float* __restrict__ bias,
                           float* __restrict__ out,
                           const float* __restrict__ wa, int layer) {
    int w = (blockIdx.x * blockDim.x + threadIdx.x) >> 5;
    int lane = threadIdx.x & 31;
    if (w >= NN) return;
    int beg = g_off[w], end = g_off[w + 1];
    int c0 = lane * 4;
    float4 acc = make_float4(0.f, 0.f, 0.f, 0.f);

    int e = beg;
    for (; e + 1 < end; e += 2) {  // 2-deep to expose MLP
        int s0 = g_csr_src[e], s1 = g_csr_src[e + 1];
        float w0 = g_csr_w[e], w1 = g_csr_w[e + 1];
        float4 v0 = *(const float4*)&S[s0 * HD + c0];
        float4 v1 = *(const float4*)&S[s1 * HD + c0];
        acc.x = fmaf(w0, v0.x, acc.x); acc.y = fmaf(w0, v0.y, acc.y);
        acc.z = fmaf(w0, v0.z, acc.z); acc.w = fmaf(w0, v0.w, acc.w);
        acc.x = fmaf(w1, v1.x, acc.x); acc.y = fmaf(w1, v1.y, acc.y);
        acc.z = fmaf(w1, v1.z, acc.z); acc.w = fmaf(w1, v1.w, acc.w);
    }
    if (e < end) {
        int s0 = g_csr_src[e];
        float w0 = g_csr_w[e];
        float4 v0 = *(const float4*)&S[s0 * HD + c0];
        acc.x = fmaf(w0, v0.x, acc.x); acc.y = fmaf(w0, v0.y, acc.y);
        acc.z = fmaf(w0, v0.z, acc.z); acc.w = fmaf(w0, v0.w, acc.w);
    }
    float4 bb = *(const float4*)&bias[c0];
    acc.x = fmaxf(acc.x + bb.x, 0.f);
    acc.y = fmaxf(acc.y + bb.y, 0.f);
    acc.z = fmaxf(acc.z + bb.z, 0.f);
    acc.w = fmaxf(acc.w + bb.w, 0.f);
    *(float4*)&out[w * HD + c0] = acc;

    float4 wv = *(const float4*)&wa[layer * HD + c0];
    float part = acc.x * wv.x + acc.y * wv.y + acc.z * wv.z + acc.w * wv.w;
#pragma unroll
    for (int o = 16; o > 0; o >>= 1) part += __shfl_down_sync(0xffffffffu, part, o);
    if (lane == 0) {
        if (layer == 0) g_slin[w] = part;
        else            g_slin[w] += part;
    }
}

// ---------------- score: tanh(segsum(w_e * slin[src]) + ba) ----------------
__global__ void score_kernel(const float* __restrict__ ba) {
    int n = blockIdx.x * blockDim.x + threadIdx.x;
    if (n >= NN) return;
    float r = 0.f;
    int beg = g_off[n], end = g_off[n + 1];
    for (int e = beg; e < end; e++)
        r = fmaf(g_csr_w[e], g_slin[g_csr_src[e]], r);
    g_score[n] = tanhf(r + ba[0]);
}

// ---------------- segment pooling (sum + max of h*score per graph) --------
__global__ void pool_kernel() {
    int g = blockIdx.x;
    int beg = g_gstart[g], end = g_gstart[g + 1];
    int c = threadIdx.x;  // 0..383
    const float* A = (c < 128) ? g_h1 : (c < 256) ? g_h2 : g_h3;
    int cc = c & 127;
    float sum = 0.f, mx = -3.4e38f;
    for (int n = beg + blockIdx.y; n < end; n += gridDim.y) {
        float v = A[n * HD + cc] * g_score[n];
        sum += v;
        mx = fmaxf(mx, v);
    }
    atomicAdd(&g_poolsum[g * 384 + c], sum);
    atomicMax(&g_poolmax[g * 384 + c], encf(mx));
}

// ---------------- final: relu([avg, max] @ Wf + bf) -----------------------
__global__ void final_kernel(const float* __restrict__ Wf,
                             const float* __restrict__ bf,
                             float* __restrict__ out) {
    int g = blockIdx.x, j = threadIdx.x;  // 128 threads
    __shared__ float p[768];
    float cnt = (float)(g_gstart[g + 1] - g_gstart[g]);
    float inv = 1.f / fmaxf(cnt, 1.f);
    for (int k = j; k < 768; k += 128)
        p[k] = (k < 384) ? g_poolsum[g * 384 + k] * inv
                         : decf(g_poolmax[g * 384 + (k - 384)]);
    __syncthreads();
    float acc = bf[j];
#pragma unroll 8
    for (int k = 0; k < 768; k++)
        acc = fmaf(p[k], Wf[k * HD + j], acc);
    out[g * HD + j] = fmaxf(acc, 0.f);
}

// ---------------- launch ----------------
extern "C" void kernel_launch(void* const* d_in, const int* in_sizes, int n_in,
                              void* d_out, int out_size) {
    const int* ei   = (const int*)d_in[0];
    const float* ew = (const float*)d_in[1];
    const float* X  = (const float*)d_in[2];
    const int* gi   = (const int*)d_in[3];
    const float* W1 = (const float*)d_in[4];
    const float* b1 = (const float*)d_in[5];
    const float* W2 = (const float*)d_in[6];
    const float* b2 = (const float*)d_in[7];
    const float* W3 = (const float*)d_in[8];
    const float* b3 = (const float*)d_in[9];
    const float* wa = (const float*)d_in[10];
    const float* ba = (const float*)d_in[11];
    const float* Wf = (const float*)d_in[12];
    const float* bf = (const float*)d_in[13];
    float* out = (float*)d_out;

    // one-time infra (no device memory; safe across graph captures)
    static cudaStream_t s1 = nullptr;
    static cudaEvent_t ev_fork = nullptr, ev_join = nullptr;
    static bool attr_done = false;
    if (!s1) {
        cudaStreamCreateWithFlags(&s1, cudaStreamNonBlocking);
        cudaEventCreateWithFlags(&ev_fork, cudaEventDisableTiming);
        cudaEventCreateWithFlags(&ev_join, cudaEventDisableTiming);
    }
    if (!attr_done) {
        cudaFuncSetAttribute(gemm128_kernel,
                             cudaFuncAttributeMaxDynamicSharedMemorySize, 98304);
        attr_done = true;
    }

    void *pS, *ph1, *ph2, *ph3;
    cudaGetSymbolAddress(&pS,  g_S);
    cudaGetSymbolAddress(&ph1, g_h1);
    cudaGetSymbolAddress(&ph2, g_h2);
    cudaGetSymbolAddress(&ph3, g_h3);
    float* S  = (float*)pS;
    float* h1 = (float*)ph1;
    float* h2 = (float*)ph2;
    float* h3 = (float*)ph3;

    const int EB = (NE + 255) / 256;
    const int NB = (NN + 255) / 256;
    const int GEMM_GRID = (NN + 63) / 64;
    const int AGG_GRID = (NN * 32 + 255) / 256;

    // fork: GEMM1 (independent of CSR build) runs on s1 in parallel
    cudaEventRecord(ev_fork, 0);
    cudaStreamWaitEvent(s1, ev_fork, 0);
    gemm128_kernel<<<GEMM_GRID, 256, 98304, s1>>>(X, W1, S, NN);
    cudaEventRecord(ev_join, s1);

    // CSR build chain on the capture (null) stream
    zero_kernel<<<256, 256>>>();
    hist_kernel<<<EB, 256>>>(ei);
    scan_kernel<<<1, 1024>>>();
    scatter_kernel<<<EB, 256>>>(ei, ew);
    bounds_kernel<<<NB, 256>>>(gi);
    bounds_fix_kernel<<<1, 32>>>();

    // join: agg1 needs both CSR and S
    cudaStreamWaitEvent(0, ev_join, 0);
    agg_kernel<<<AGG_GRID, 256>>>(S, b1, h1, wa, 0);

    gemm128_kernel<<<GEMM_GRID, 256, 98304>>>(h1, W2, S, NN);
    agg_kernel<<<AGG_GRID, 256>>>(S, b2, h2, wa, 1);

    gemm128_kernel<<<GEMM_GRID, 256, 98304>>>(h2, W3, S, NN);
    agg_kernel<<<AGG_GRID, 256>>>(S, b3, h3, wa, 2);

    score_kernel<<<NB, 256>>>(ba);
    pool_kernel<<<dim3(NG, 16), 384>>>();
    final_kernel<<<NG, 128>>>(Wf, bf, out);
}

// round 4
// speedup vs baseline: 1.1670x; 1.1670x over previous
#include <cuda_runtime.h>
#include <math.h>

#define NN 50000
#define NE 800000
#define HD 128
#define NG 64

// ---------------- scratch (device globals: allocation-free) ----------------
__device__ int      g_deg[NN];
__device__ int      g_fill[NN];      // running insert cursor (starts = offsets)
__device__ int      g_off[NN + 1];
__device__ int      g_csr_src[NE];
__device__ float    g_csr_w[NE];
__device__ float    g_S [NN * HD];   // GEMM output (support)
__device__ float    g_h1[NN * HD];
__device__ float    g_h2[NN * HD];
__device__ float    g_h3[NN * HD];
__device__ float    g_slin[NN];      // h @ wa (accumulated per layer)
__device__ float    g_score[NN];
__device__ float    g_poolsum[NG * 3 * HD];
__device__ unsigned g_poolmax[NG * 3 * HD];
__device__ int      g_gstart[NG + 1];

// monotonic float<->uint encoding for atomicMax on floats
__device__ __forceinline__ unsigned encf(float f) {
    unsigned u = __float_as_uint(f);
    return (u & 0x80000000u) ? ~u : (u | 0x80000000u);
}
__device__ __forceinline__ float decf(unsigned u) {
    return __uint_as_float((u & 0x80000000u) ? (u ^ 0x80000000u) : ~u);
}

// ---------------- init ----------------
__global__ void zero_kernel() {
    int i = blockIdx.x * blockDim.x + threadIdx.x;
    int stride = gridDim.x * blockDim.x;
    for (int j = i; j < NN; j += stride) g_deg[j] = 0;
    for (int j = i; j < NG * 3 * HD; j += stride) { g_poolsum[j] = 0.f; g_poolmax[j] = 0u; }
    if (i < NG + 1) g_gstart[i] = 0;
}

// ---------------- CSR build (edge_index is int32: JAX x64 disabled) -------
__global__ void hist_kernel(const int* __restrict__ ei) {
    int e = blockIdx.x * blockDim.x + threadIdx.x;
    if (e < NE) {
        unsigned d = (unsigned)ei[NE + e];  // row 1 = dst
        if (d < NN) atomicAdd(&g_deg[d], 1);
    }
}

// smem-staged single-block scan: coalesced in, scan in smem, coalesced out.
// Produces g_off (exclusive prefix) AND g_fill (= g_off copy, scatter cursor).
__global__ void scan_kernel() {
    extern __shared__ int ssc[];          // [NN] values + [1024] partials
    int* part = ssc + NN;
    int t = threadIdx.x;

    for (int i = t; i < NN; i += 1024) ssc[i] = g_deg[i];
    __syncthreads();

    const int ITEMS = 49;  // 1024*49 = 50176 >= 50000
    int base = t * ITEMS;
    int s = 0;
#pragma unroll
    for (int i = 0; i < ITEMS; i++) {
        int idx = base + i;
        if (idx < NN) s += ssc[idx];
    }
    part[t] = s;
    __syncthreads();
    for (int d = 1; d < 1024; d <<= 1) {
        int v = 0;
        if (t >= d) v = part[t - d];
        __syncthreads();
        part[t] += v;
        __syncthreads();
    }
    int run = part[t] - s;  // exclusive base for this chunk
#pragma unroll
    for (int i = 0; i < ITEMS; i++) {
        int idx = base + i;
        if (idx < NN) { int d = ssc[idx]; ssc[idx] = run; run += d; }
    }
    if (t == 1023) g_off[NN] = part[1023];
    __syncthreads();

    for (int i = t; i < NN; i += 1024) {
        int v = ssc[i];
        g_off[i] = v;
        g_fill[i] = v;
    }
}

__global__ void scatter_kernel(const int* __restrict__ ei,
                               const float* __restrict__ ew) {
    int e = blockIdx.x * blockDim.x + threadIdx.x;
    if (e >= NE) return;
    unsigned d = (unsigned)ei[NE + e];
    unsigned s = (unsigned)ei[e];
    if (d >= NN || s >= NN) return;
    int pos = atomicAdd(&g_fill[d], 1);
    g_csr_src[pos] = (int)s;
    g_csr_w[pos] = ew[e];
}

__global__ void bounds_kernel(const int* __restrict__ gi) {
    int n = blockIdx.x * blockDim.x + threadIdx.x;
    if (n >= NN) return;
    int g = gi[n];
    if ((unsigned)g >= NG) return;
    if (n == 0) g_gstart[g] = 0;
    else if (gi[n - 1] != g) g_gstart[g] = n;
    if (n == NN - 1) g_gstart[NG] = NN;
}

__global__ void bounds_fix_kernel() {
    if (threadIdx.x == 0) {
        for (int g = NG - 1; g >= 1; g--)
            if (g_gstart[g] == 0 && g_gstart[g - 1] != 0) g_gstart[g] = g_gstart[g + 1];
    }
}

// ---------------- GEMM: S = X @ W  (X: [nrows,128], W: [128,128]) ---------
// block = 256 threads, tile = 64 rows x 128 cols, thread = 8 rows x 4 cols
__global__ void gemm128_kernel(const float* __restrict__ X,
                               const float* __restrict__ W,
                               float* __restrict__ S, int nrows) {
    extern __shared__ float sh[];
    float* Wsh = sh;              // 128*128
    float* Xsh = sh + HD * HD;    // 64*128
    int tid = threadIdx.x;
    int rbase = blockIdx.x * 64;

#pragma unroll
    for (int i = 0; i < 16; i++) {
        int f = tid + i * 256;  // float4 idx, 4096 total
        ((float4*)Wsh)[f] = ((const float4*)W)[f];
    }
#pragma unroll
    for (int i = 0; i < 8; i++) {
        int f = tid + i * 256;  // float4 idx, 2048 total
        int row = rbase + (f >> 5);
        float4 v = make_float4(0.f, 0.f, 0.f, 0.f);
        if (row < nrows) v = ((const float4*)X)[row * 32 + (f & 31)];
        ((float4*)Xsh)[f] = v;
    }
    __syncthreads();

    int tx = tid & 31, ty = tid >> 5;
    int c0 = tx * 4, r0 = ty * 8;
    float4 acc[8];
#pragma unroll
    for (int rr = 0; rr < 8; rr++) acc[rr] = make_float4(0.f, 0.f, 0.f, 0.f);

#pragma unroll 4
    for (int k = 0; k < HD; k += 4) {
        float4 w0 = *(float4*)&Wsh[(k + 0) * HD + c0];
        float4 w1 = *(float4*)&Wsh[(k + 1) * HD + c0];
        float4 w2 = *(float4*)&Wsh[(k + 2) * HD + c0];
        float4 w3 = *(float4*)&Wsh[(k + 3) * HD + c0];
#pragma unroll
        for (int rr = 0; rr < 8; rr++) {
            float4 xv = *(float4*)&Xsh[(r0 + rr) * HD + k];
            acc[rr].x = fmaf(xv.x, w0.x, acc[rr].x);
            acc[rr].y = fmaf(xv.x, w0.y, acc[rr].y);
            acc[rr].z = fmaf(xv.x, w0.z, acc[rr].z);
            acc[rr].w = fmaf(xv.x, w0.w, acc[rr].w);
            acc[rr].x = fmaf(xv.y, w1.x, acc[rr].x);
            acc[rr].y = fmaf(xv.y, w1.y, acc[rr].y);
            acc[rr].z = fmaf(xv.y, w1.z, acc[rr].z);
            acc[rr].w = fmaf(xv.y, w1.w, acc[rr].w);
            acc[rr].x = fmaf(xv.z, w2.x, acc[rr].x);
            acc[rr].y = fmaf(xv.z, w2.y, acc[rr].y);
            acc[rr].z = fmaf(xv.z, w2.z, acc[rr].z);
            acc[rr].w = fmaf(xv.z, w2.w, acc[rr].w);
            acc[rr].x = fmaf(xv.w, w3.x, acc[rr].x);
            acc[rr].y = fmaf(xv.w, w3.y, acc[rr].y);
            acc[rr].z = fmaf(xv.w, w3.z, acc[rr].z);
            acc[rr].w = fmaf(xv.w, w3.w, acc[rr].w);
        }
    }
#pragma unroll
    for (int rr = 0; rr < 8; rr++) {
        int row = rbase + r0 + rr;
        if (row < nrows) *(float4*)&S[row * HD + c0] = acc[rr];
    }
}

// ---------------- aggregation: out[n] = relu(b + sum_e w_e * S[src_e]) ----
// one warp per dst node; fused partial of slin = dot(out_row, wa_segment)
__global__ void agg_kernel(const float* __restrict__ S,
                           const float* __restrict__ bias,
                           float* __restrict__ out,
                           const float* __restrict__ wa, int layer) {
    int w = (blockIdx.x * blockDim.x + threadIdx.x) >> 5;
    int lane = threadIdx.x & 31;
    if (w >= NN) return;
    int beg = g_off[w], end = g_off[w + 1];
    int c0 = lane * 4;
    float4 acc = make_float4(0.f, 0.f, 0.f, 0.f);

    int e = beg;
    for (; e + 1 < end; e += 2) {  // 2-deep to expose MLP
        int s0 = g_csr_src[e], s1 = g_csr_src[e + 1];
        float w0 = g_csr_w[e], w1 = g_csr_w[e + 1];
        float4 v0 = *(const float4*)&S[s0 * HD + c0];
        float4 v1 = *(const float4*)&S[s1 * HD + c0];
        acc.x = fmaf(w0, v0.x, acc.x); acc.y = fmaf(w0, v0.y, acc.y);
        acc.z = fmaf(w0, v0.z, acc.z); acc.w = fmaf(w0, v0.w, acc.w);
        acc.x = fmaf(w1, v1.x, acc.x); acc.y = fmaf(w1, v1.y, acc.y);
        acc.z = fmaf(w1, v1.z, acc.z); acc.w = fmaf(w1, v1.w, acc.w);
    }
    if (e < end) {
        int s0 = g_csr_src[e];
        float w0 = g_csr_w[e];
        float4 v0 = *(const float4*)&S[s0 * HD + c0];
        acc.x = fmaf(w0, v0.x, acc.x); acc.y = fmaf(w0, v0.y, acc.y);
        acc.z = fmaf(w0, v0.z, acc.z); acc.w = fmaf(w0, v0.w, acc.w);
    }
    float4 bb = *(const float4*)&bias[c0];
    acc.x = fmaxf(acc.x + bb.x, 0.f);
    acc.y = fmaxf(acc.y + bb.y, 0.f);
    acc.z = fmaxf(acc.z + bb.z, 0.f);
    acc.w = fmaxf(acc.w + bb.w, 0.f);
    *(float4*)&out[w * HD + c0] = acc;

    float4 wv = *(const float4*)&wa[layer * HD + c0];
    float part = acc.x * wv.x + acc.y * wv.y + acc.z * wv.z + acc.w * wv.w;
#pragma unroll
    for (int o = 16; o > 0; o >>= 1) part += __shfl_down_sync(0xffffffffu, part, o);
    if (lane == 0) {
        if (layer == 0) g_slin[w] = part;
        else            g_slin[w] += part;
    }
}

// ---------------- score: tanh(segsum(w_e * slin[src]) + ba) ----------------
__global__ void score_kernel(const float* __restrict__ ba) {
    int n = blockIdx.x * blockDim.x + threadIdx.x;
    if (n >= NN) return;
    float r = 0.f;
    int beg = g_off[n], end = g_off[n + 1];
    for (int e = beg; e < end; e++)
        r = fmaf(g_csr_w[e], g_slin[g_csr_src[e]], r);
    g_score[n] = tanhf(r + ba[0]);
}

// ---------------- segment pooling (sum + max of h*score per graph) --------
__global__ void pool_kernel() {
    int g = blockIdx.x;
    int beg = g_gstart[g], end = g_gstart[g + 1];
    int c = threadIdx.x;  // 0..383
    const float* A = (c < 128) ? g_h1 : (c < 256) ? g_h2 : g_h3;
    int cc = c & 127;
    float sum = 0.f, mx = -3.4e38f;
    for (int n = beg + blockIdx.y; n < end; n += gridDim.y) {
        float v = A[n * HD + cc] * g_score[n];
        sum += v;
        mx = fmaxf(mx, v);
    }
    atomicAdd(&g_poolsum[g * 384 + c], sum);
    atomicMax(&g_poolmax[g * 384 + c], encf(mx));
}

// ---------------- final: relu([avg, max] @ Wf + bf) -----------------------
__global__ void final_kernel(const float* __restrict__ Wf,
                             const float* __restrict__ bf,
                             float* __restrict__ out) {
    int g = blockIdx.x, j = threadIdx.x;  // 128 threads
    __shared__ float p[768];
    float cnt = (float)(g_gstart[g + 1] - g_gstart[g]);
    float inv = 1.f / fmaxf(cnt, 1.f);
    for (int k = j; k < 768; k += 128)
        p[k] = (k < 384) ? g_poolsum[g * 384 + k] * inv
                         : decf(g_poolmax[g * 384 + (k - 384)]);
    __syncthreads();
    float acc = bf[j];
#pragma unroll 8
    for (int k = 0; k < 768; k++)
        acc = fmaf(p[k], Wf[k * HD + j], acc);
    out[g * HD + j] = fmaxf(acc, 0.f);
}

// ---------------- launch ----------------
extern "C" void kernel_launch(void* const* d_in, const int* in_sizes, int n_in,
                              void* d_out, int out_size) {
    const int* ei   = (const int*)d_in[0];
    const float* ew = (const float*)d_in[1];
    const float* X  = (const float*)d_in[2];
    const int* gi   = (const int*)d_in[3];
    const float* W1 = (const float*)d_in[4];
    const float* b1 = (const float*)d_in[5];
    const float* W2 = (const float*)d_in[6];
    const float* b2 = (const float*)d_in[7];
    const float* W3 = (const float*)d_in[8];
    const float* b3 = (const float*)d_in[9];
    const float* wa = (const float*)d_in[10];
    const float* ba = (const float*)d_in[11];
    const float* Wf = (const float*)d_in[12];
    const float* bf = (const float*)d_in[13];
    float* out = (float*)d_out;

    // one-time infra (no device memory; safe across graph captures)
    static cudaStream_t s1 = nullptr;
    static cudaEvent_t ev_fork = nullptr, ev_join = nullptr;
    static bool attr_done = false;
    if (!s1) {
        cudaStreamCreateWithFlags(&s1, cudaStreamNonBlocking);
        cudaEventCreateWithFlags(&ev_fork, cudaEventDisableTiming);
        cudaEventCreateWithFlags(&ev_join, cudaEventDisableTiming);
    }
    if (!attr_done) {
        cudaFuncSetAttribute(gemm128_kernel,
                             cudaFuncAttributeMaxDynamicSharedMemorySize, 98304);
        cudaFuncSetAttribute(scan_kernel,
                             cudaFuncAttributeMaxDynamicSharedMemorySize,
                             (NN + 1024) * 4);
        attr_done = true;
    }

    void *pS, *ph1, *ph2, *ph3;
    cudaGetSymbolAddress(&pS,  g_S);
    cudaGetSymbolAddress(&ph1, g_h1);
    cudaGetSymbolAddress(&ph2, g_h2);
    cudaGetSymbolAddress(&ph3, g_h3);
    float* S  = (float*)pS;
    float* h1 = (float*)ph1;
    float* h2 = (float*)ph2;
    float* h3 = (float*)ph3;

    const int EB = (NE + 255) / 256;
    const int NB = (NN + 255) / 256;
    const int GEMM_GRID = (NN + 63) / 64;
    const int AGG_GRID = (NN * 32 + 255) / 256;

    // fork: GEMM1 (independent of CSR build) runs on s1 in parallel
    cudaEventRecord(ev_fork, 0);
    cudaStreamWaitEvent(s1, ev_fork, 0);
    gemm128_kernel<<<GEMM_GRID, 256, 98304, s1>>>(X, W1, S, NN);
    cudaEventRecord(ev_join, s1);

    // CSR build chain on the capture (null) stream
    zero_kernel<<<256, 256>>>();
    hist_kernel<<<EB, 256>>>(ei);
    scan_kernel<<<1, 1024, (NN + 1024) * 4>>>();
    scatter_kernel<<<EB, 256>>>(ei, ew);
    bounds_kernel<<<NB, 256>>>(gi);
    bounds_fix_kernel<<<1, 32>>>();

    // join: agg1 needs both CSR and S
    cudaStreamWaitEvent(0, ev_join, 0);
    agg_kernel<<<AGG_GRID, 256>>>(S, b1, h1, wa, 0);

    gemm128_kernel<<<GEMM_GRID, 256, 98304>>>(h1, W2, S, NN);
    agg_kernel<<<AGG_GRID, 256>>>(S, b2, h2, wa, 1);

    gemm128_kernel<<<GEMM_GRID, 256, 98304>>>(h2, W3, S, NN);
    agg_kernel<<<AGG_GRID, 256>>>(S, b3, h3, wa, 2);

    score_kernel<<<NB, 256>>>(ba);
    pool_kernel<<<dim3(NG, 16), 384>>>();
    final_kernel<<<NG, 128>>>(Wf, bf, out);
}